// round 7
// baseline (speedup 1.0000x reference)
#include <cuda_runtime.h>

#define TOTAL_OPS 102400
#define ND 1024
#define NW 64
#define E 256
#define H1N 32
#define H2N 16

// ---------------- device scratch (no allocations allowed) ----------------
__device__ float    g_logits[TOTAL_OPS];
__device__ float    g_yw_op[ND * H1N];
__device__ float    g_yw_pr[ND * H1N];
__device__ unsigned g_maxbits;
__device__ float    g_sum;
__device__ unsigned g_cnt;

typedef unsigned long long ull;

// ---------------- packed fp32x2 helpers (sm_103a FFMA2 path) ----------------
__device__ __forceinline__ ull fma2(ull a, ull b, ull c) {
    ull d;
    asm("fma.rn.f32x2 %0, %1, %2, %3;" : "=l"(d) : "l"(a), "l"(b), "l"(c));
    return d;
}
__device__ __forceinline__ ull splat2(float x) {
    ull d;
    asm("mov.b64 %0, {%1, %1};" : "=l"(d) : "f"(x));
    return d;
}
__device__ __forceinline__ void unpack2(ull v, float& lo, float& hi) {
    asm("mov.b64 {%0, %1}, %2;" : "=f"(lo), "=f"(hi) : "l"(v));
}

// monotone float -> unsigned map for atomicMax
__device__ __forceinline__ unsigned encf(float f) {
    unsigned b = __float_as_uint(f);
    return (b & 0x80000000u) ? ~b : (b | 0x80000000u);
}
__device__ __forceinline__ float decf(unsigned u) {
    return (u & 0x80000000u) ? __uint_as_float(u & 0x7FFFFFFFu)
                             : __uint_as_float(~u);
}

// ---------------- K1: per-dag tables yW = y@W1y + (b1 + z@W1z) --------------
// 32 blocks x 128 thr; blocks 0-15 op table, 16-31 pr table; 2 threads/dag.
// Also: block 0 resets the softmax scalars (runs before k_ops in-stream).
__global__ void __launch_bounds__(128) k_pre(
    const float* __restrict__ opW1, const float* __restrict__ opb1,
    const float* __restrict__ prW1, const float* __restrict__ prb1,
    const float* __restrict__ z, const float* __restrict__ y)
{
    __shared__ __align__(16) float sW[E * H1N];    // 32 KB y-part of W1
    __shared__ float szc[H1N];
    int b = blockIdx.x;
    int t = threadIdx.x;
    int table = b >> 4;                 // 0 = op, 1 = pr
    int d0 = (b & 15) * 64;
    const float* W1 = table ? prW1 : opW1;
    const float* b1 = table ? prb1 : opb1;
    int f4off = table ? (1 * H1N / 4) : (E * H1N / 4);
    int offZ  = table ? (E + 1) : (2 * E);
    float* outT = table ? g_yw_pr : g_yw_op;

    if (b == 0 && t == 0) { g_maxbits = 0u; g_sum = 0.f; g_cnt = 0u; }

    const float4* gW4 = (const float4*)W1;
    float4* sW4 = (float4*)sW;
#pragma unroll
    for (int i = 0; i < 16; i++) sW4[i * 128 + t] = gW4[f4off + i * 128 + t];

    // z-projection: 4 threads per output j, 64 k each
    {
        int j = t >> 2, sub = t & 3;
        const float* Wz = W1 + (size_t)(offZ + sub * 64) * H1N + j;
        float c = 0.f;
#pragma unroll 8
        for (int kk = 0; kk < 64; kk++) c += z[sub * 64 + kk] * Wz[kk * H1N];
        c += __shfl_xor_sync(0xffffffffu, c, 1);
        c += __shfl_xor_sync(0xffffffffu, c, 2);
        if (sub == 0) szc[j] = c + b1[j];
    }
    __syncthreads();

    int d = d0 + (t >> 1);              // 64 dags per block, 2 threads each
    int half = t & 1;
    ull acc[16];
#pragma unroll
    for (int q = 0; q < 16; q++) acc[q] = 0ull;
    const float4* yr = (const float4*)&y[d * E];
    const ulonglong2* sWu = (const ulonglong2*)sW;

    int kc0 = half * 32;
    float4 va = yr[kc0];
    for (int kc = 0; kc < 32; kc++) {
        float4 pa = yr[kc0 + ((kc + 1) & 31)];
        float f[4] = {va.x, va.y, va.z, va.w};
#pragma unroll
        for (int kk = 0; kk < 4; kk++) {
            ull xd = splat2(f[kk]);
            const ulonglong2* w = &sWu[((kc0 + kc) * 4 + kk) * 8];
#pragma unroll
            for (int q = 0; q < 8; q++) {
                ulonglong2 wv = w[q];
                acc[2 * q]     = fma2(xd, wv.x, acc[2 * q]);
                acc[2 * q + 1] = fma2(xd, wv.y, acc[2 * q + 1]);
            }
        }
        va = pa;
    }
    float h[H1N];
#pragma unroll
    for (int q = 0; q < 16; q++) unpack2(acc[q], h[2 * q], h[2 * q + 1]);
#pragma unroll
    for (int j = 0; j < H1N; j++)
        h[j] += __shfl_xor_sync(0xffffffffu, h[j], 1);
    if (half == 0) {
#pragma unroll
        for (int j = 0; j < H1N; j++) outT[d * H1N + j] = h[j] + szc[j];
    }
}

// ---------------- K2: prlvl branch, 8 dags/block ----------------
__global__ void __launch_bounds__(512) k_prlvl(
    const float* __restrict__ prW1, const float* __restrict__ prW2,
    const float* __restrict__ prb2, const float* __restrict__ prW3,
    const float* __restrict__ prb3, const float* __restrict__ msk,
    float* __restrict__ out, int nops)
{
    __shared__ __align__(16) float sW2[H1N * H2N];
    __shared__ float sb2[H2N], sW3[H2N];
    __shared__ float sb3;
    __shared__ float sw1[H1N];
    __shared__ float sbase[8 * H1N];
    __shared__ float redm[8][2], reds[8][2];

    int t = threadIdx.x;
    int g = t >> 6;                       // dag group 0..7
    int w = t & 63;                       // worker
    int d = blockIdx.x * 8 + g;

    if (t < H1N * H2N) sW2[t] = prW2[t];
    if (t < H2N) { sb2[t] = prb2[t]; sW3[t] = prW3[t]; }
    if (t == 0) sb3 = prb3[0];
    if (t < H1N) sw1[t] = prW1[t];        // limit row of W1
    if (t < 8 * H1N) sbase[t] = g_yw_pr[blockIdx.x * 8 * H1N + t];
    __syncthreads();

    float limit = (float)(w + 1);
    const float* base = &sbase[g * H1N];
    float h2[H2N];
#pragma unroll
    for (int j2 = 0; j2 < H2N; j2++) h2[j2] = sb2[j2];
#pragma unroll
    for (int j = 0; j < H1N; j++) {
        float v = fmaxf(base[j] + limit * sw1[j], 0.f);
        const float4* w2 = (const float4*)&sW2[j * H2N];
#pragma unroll
        for (int q2 = 0; q2 < 4; q2++) {
            float4 wv = w2[q2];
            h2[4 * q2 + 0] += v * wv.x;
            h2[4 * q2 + 1] += v * wv.y;
            h2[4 * q2 + 2] += v * wv.z;
            h2[4 * q2 + 3] += v * wv.w;
        }
    }
    float logit = sb3;
#pragma unroll
    for (int j2 = 0; j2 < H2N; j2++) logit += fmaxf(h2[j2], 0.f) * sW3[j2];
    logit -= (1.f - msk[d * NW + w]) * 1000.f;

    float m = logit;
#pragma unroll
    for (int o = 16; o > 0; o >>= 1) m = fmaxf(m, __shfl_xor_sync(0xffffffffu, m, o));
    if ((w & 31) == 0) redm[g][w >> 5] = m;
    __syncthreads();
    m = fmaxf(redm[g][0], redm[g][1]);
    float e = expf(logit - m);
    float s = e;
#pragma unroll
    for (int o = 16; o > 0; o >>= 1) s += __shfl_xor_sync(0xffffffffu, s, o);
    if ((w & 31) == 0) reds[g][w >> 5] = s;
    __syncthreads();
    s = reds[g][0] + reds[g][1];
    out[nops + d * NW + w] = e / s;
}

// ---------------- K3: op MLP, 4 rows x 16 cols per thread -------------------
__global__ void __launch_bounds__(128, 4) k_ops(
    const float* __restrict__ x, const float* __restrict__ opW1,
    const float* __restrict__ opW2, const float* __restrict__ opb2,
    const float* __restrict__ opW3, const float* __restrict__ opb3,
    const float* __restrict__ op_msk, const int* __restrict__ num_ops,
    int nrows)
{
    __shared__ __align__(16) float sBuf[256 * 33];  // weights (8192) / h1 stage
    __shared__ int sCum[ND];
    __shared__ __align__(16) float sW2[H1N * H2N];
    __shared__ float sb2[H2N], sW3[H2N];
    __shared__ float sb3;
    __shared__ float wmax[4];
    __shared__ int wsum[4];

    int t = threadIdx.x;
    // --- stage W1 x-part (rows 0..255) ---
    const float4* gW4 = (const float4*)opW1;
    float4* sW4 = (float4*)sBuf;
#pragma unroll
    for (int i = 0; i < 16; i++) sW4[i * 128 + t] = gW4[i * 128 + t];
    for (int i = t; i < H1N * H2N; i += 128) sW2[i] = opW2[i];
    if (t < H2N) { sb2[t] = opb2[t]; sW3[t] = opW3[t]; }
    if (t == 0) sb3 = opb3[0];

    // --- inline inclusive scan of num_ops into sCum ---
    {
        int vloc[8]; int tsum = 0;
#pragma unroll
        for (int i = 0; i < 8; i++) { vloc[i] = num_ops[t * 8 + i]; tsum += vloc[i]; }
        int lane = t & 31, wid = t >> 5;
        int sc = tsum;
#pragma unroll
        for (int o = 1; o < 32; o <<= 1) {
            int nv = __shfl_up_sync(0xffffffffu, sc, o);
            if (lane >= o) sc += nv;
        }
        if (lane == 31) wsum[wid] = sc;
        __syncthreads();
        int woff = 0;
#pragma unroll
        for (int q = 0; q < 4; q++) if (q < wid) woff += wsum[q];
        int run = woff + sc - tsum;      // exclusive prefix for this thread
#pragma unroll
        for (int i = 0; i < 8; i++) { run += vloc[i]; sCum[t * 8 + i] = run; }
    }
    __syncthreads();

    // --- main GEMM loop ---
    int colhalf = t >> 6;               // warps 0-1: cols 0-15, warps 2-3: 16-31
    int rt = t & 63;                    // row-thread 0..63
    int row0 = blockIdx.x * 256;

    const float4* x0 = (const float4*)&x[(size_t)min(row0 + rt,       nrows - 1) * E];
    const float4* x1 = (const float4*)&x[(size_t)min(row0 + rt + 64,  nrows - 1) * E];
    const float4* x2 = (const float4*)&x[(size_t)min(row0 + rt + 128, nrows - 1) * E];
    const float4* x3 = (const float4*)&x[(size_t)min(row0 + rt + 192, nrows - 1) * E];

    ull a0[8], a1[8], a2[8], a3[8];
#pragma unroll
    for (int q = 0; q < 8; q++) { a0[q] = 0ull; a1[q] = 0ull; a2[q] = 0ull; a3[q] = 0ull; }
    const ulonglong2* sWu = (const ulonglong2*)sBuf;

    float4 v0 = x0[0], v1 = x1[0], v2 = x2[0], v3 = x3[0];
    for (int kc = 0; kc < 64; kc++) {
        int kn = (kc + 1) & 63;
        float4 p0 = x0[kn], p1 = x1[kn], p2 = x2[kn], p3 = x3[kn];
        float f0[4] = {v0.x, v0.y, v0.z, v0.w};
        float f1[4] = {v1.x, v1.y, v1.z, v1.w};
        float f2[4] = {v2.x, v2.y, v2.z, v2.w};
        float f3[4] = {v3.x, v3.y, v3.z, v3.w};
#pragma unroll
        for (int kk = 0; kk < 4; kk++) {
            ull s0 = splat2(f0[kk]);
            ull s1 = splat2(f1[kk]);
            ull s2 = splat2(f2[kk]);
            ull s3 = splat2(f3[kk]);
            const ulonglong2* w = &sWu[(kc * 4 + kk) * 8 + colhalf * 4];
            ulonglong2 w0 = w[0], w1 = w[1], w2 = w[2], w3 = w[3];
            a0[0] = fma2(s0, w0.x, a0[0]); a0[1] = fma2(s0, w0.y, a0[1]);
            a0[2] = fma2(s0, w1.x, a0[2]); a0[3] = fma2(s0, w1.y, a0[3]);
            a0[4] = fma2(s0, w2.x, a0[4]); a0[5] = fma2(s0, w2.y, a0[5]);
            a0[6] = fma2(s0, w3.x, a0[6]); a0[7] = fma2(s0, w3.y, a0[7]);
            a1[0] = fma2(s1, w0.x, a1[0]); a1[1] = fma2(s1, w0.y, a1[1]);
            a1[2] = fma2(s1, w1.x, a1[2]); a1[3] = fma2(s1, w1.y, a1[3]);
            a1[4] = fma2(s1, w2.x, a1[4]); a1[5] = fma2(s1, w2.y, a1[5]);
            a1[6] = fma2(s1, w3.x, a1[6]); a1[7] = fma2(s1, w3.y, a1[7]);
            a2[0] = fma2(s2, w0.x, a2[0]); a2[1] = fma2(s2, w0.y, a2[1]);
            a2[2] = fma2(s2, w1.x, a2[2]); a2[3] = fma2(s2, w1.y, a2[3]);
            a2[4] = fma2(s2, w2.x, a2[4]); a2[5] = fma2(s2, w2.y, a2[5]);
            a2[6] = fma2(s2, w3.x, a2[6]); a2[7] = fma2(s2, w3.y, a2[7]);
            a3[0] = fma2(s3, w0.x, a3[0]); a3[1] = fma2(s3, w0.y, a3[1]);
            a3[2] = fma2(s3, w1.x, a3[2]); a3[3] = fma2(s3, w1.y, a3[3]);
            a3[4] = fma2(s3, w2.x, a3[4]); a3[5] = fma2(s3, w2.y, a3[5]);
            a3[6] = fma2(s3, w3.x, a3[6]); a3[7] = fma2(s3, w3.y, a3[7]);
        }
        v0 = p0; v1 = p1; v2 = p2; v3 = p3;
    }

    // --- stage h1 partials to SMEM (stride-33, conflict-free), reuse sBuf ---
    __syncthreads();
    {
        float* dst0 = &sBuf[(rt      ) * 33 + colhalf * 16];
        float* dst1 = &sBuf[(rt +  64) * 33 + colhalf * 16];
        float* dst2 = &sBuf[(rt + 128) * 33 + colhalf * 16];
        float* dst3 = &sBuf[(rt + 192) * 33 + colhalf * 16];
#pragma unroll
        for (int q = 0; q < 8; q++) {
            unpack2(a0[q], dst0[2 * q], dst0[2 * q + 1]);
            unpack2(a1[q], dst1[2 * q], dst1[2 * q + 1]);
            unpack2(a2[q], dst2[2 * q], dst2[2 * q + 1]);
            unpack2(a3[q], dst3[2 * q], dst3[2 * q + 1]);
        }
    }
    __syncthreads();

    // --- epilogue: 2 rows per thread ---
    float m = -3.402823466e38f;
#pragma unroll
    for (int r = 0; r < 2; r++) {
        int lr = t + r * 128;
        int i = row0 + lr;
        if (i < nrows) {
            // dag = max{ d : exclusive_cum[d] <= i }
            int d = 0;
#pragma unroll
            for (int s = 512; s > 0; s >>= 1)
                if (d + s <= ND - 1 && sCum[d + s - 1] <= i) d += s;
            const float* hs = &sBuf[lr * 33];
            const float* bw = &g_yw_op[d * H1N];
            float h2[H2N];
#pragma unroll
            for (int j2 = 0; j2 < H2N; j2++) h2[j2] = sb2[j2];
#pragma unroll
            for (int j = 0; j < H1N; j++) {
                float v = fmaxf(hs[j] + bw[j], 0.f);
                const float4* w2 = (const float4*)&sW2[j * H2N];
#pragma unroll
                for (int q2 = 0; q2 < 4; q2++) {
                    float4 wv = w2[q2];
                    h2[4 * q2 + 0] += v * wv.x;
                    h2[4 * q2 + 1] += v * wv.y;
                    h2[4 * q2 + 2] += v * wv.z;
                    h2[4 * q2 + 3] += v * wv.w;
                }
            }
            float logit = sb3;
#pragma unroll
            for (int j2 = 0; j2 < H2N; j2++) logit += fmaxf(h2[j2], 0.f) * sW3[j2];
            logit -= (1.f - op_msk[i]) * 1000.f;
            g_logits[i] = logit;
            m = fmaxf(m, logit);
        }
    }
#pragma unroll
    for (int o = 16; o > 0; o >>= 1) m = fmaxf(m, __shfl_xor_sync(0xffffffffu, m, o));
    if ((t & 31) == 0) wmax[t >> 5] = m;
    __syncthreads();
    if (t == 0) {
        float bm = fmaxf(fmaxf(wmax[0], wmax[1]), fmaxf(wmax[2], wmax[3]));
        atomicMax(&g_maxbits, encf(bm));
    }
}

// ---------------- K4: fused exp + global sum + normalize (spin barrier) ------
__global__ void __launch_bounds__(256) k_sum_norm(float* __restrict__ out, int n) {
    __shared__ float sp[8];
    __shared__ float sInv;
    int t = threadIdx.x;
    int i = blockIdx.x * 256 + t;
    float gm = decf(g_maxbits);
    float e = 0.f;
    if (i < n) e = expf(g_logits[i] - gm);

    float s = e;
#pragma unroll
    for (int o = 16; o > 0; o >>= 1) s += __shfl_xor_sync(0xffffffffu, s, o);
    if ((t & 31) == 0) sp[t >> 5] = s;
    __syncthreads();
    if (t == 0) {
        float bs = 0.f;
#pragma unroll
        for (int w = 0; w < 8; w++) bs += sp[w];
        atomicAdd(&g_sum, bs);
        __threadfence();
        atomicAdd(&g_cnt, 1u);
        volatile unsigned* vc = &g_cnt;
        while (*vc < gridDim.x) { }
        __threadfence();
        sInv = 1.f / *((volatile float*)&g_sum);
    }
    __syncthreads();
    if (i < n) out[i] = e * sInv;
}

// ---------------- launcher ----------------
extern "C" void kernel_launch(void* const* d_in, const int* in_sizes, int n_in,
                              void* d_out, int out_size) {
    int o = (n_in >= 20) ? 2 : 0;
    const int*   num_ops = (const int*)d_in[0];
    const float* x       = (const float*)d_in[1 + o];
    const float* y       = (const float*)d_in[2 + o];
    const float* z       = (const float*)d_in[3 + o];
    const float* op_msk  = (const float*)d_in[4 + o];
    const float* pr_msk  = (const float*)d_in[5 + o];
    const float* opW1    = (const float*)d_in[6 + o];
    const float* opb1    = (const float*)d_in[7 + o];
    const float* opW2    = (const float*)d_in[8 + o];
    const float* opb2    = (const float*)d_in[9 + o];
    const float* opW3    = (const float*)d_in[10 + o];
    const float* opb3    = (const float*)d_in[11 + o];
    const float* prW1    = (const float*)d_in[12 + o];
    const float* prb1    = (const float*)d_in[13 + o];
    const float* prW2    = (const float*)d_in[14 + o];
    const float* prb2    = (const float*)d_in[15 + o];
    const float* prW3    = (const float*)d_in[16 + o];
    const float* prb3    = (const float*)d_in[17 + o];
    float* out = (float*)d_out;

    int n = in_sizes[1 + o] / E;   // total ops (102400)

    k_pre<<<32, 128>>>(opW1, opb1, prW1, prb1, z, y);
    k_prlvl<<<ND / 8, 512>>>(prW1, prW2, prb2, prW3, prb3, pr_msk, out, n);
    k_ops<<<(n + 255) / 256, 128>>>(x, opW1, opW2, opb2, opW3, opb3, op_msk, num_ops, n);
    k_sum_norm<<<(n + 255) / 256, 256>>>(out, n);
}